// round 13
// baseline (speedup 1.0000x reference)
#include <cuda_runtime.h>

#define N 512
#define D 256
#define KSPLIT 8

// Scratch (device globals — no allocation allowed)
__device__ float g_q[N * N];
__device__ float g_k[N * N];
__device__ float g_v[N * N];
__device__ float g_s[N * N];
__device__ float g_sp[KSPLIT][N * N];   // split-K partials of q@k
__device__ float g_op[KSPLIT][N * N];   // split-K partials of s@v

#define PROJ_BLOCKS 1184   // 148 * 8 (persistent single wave)

__device__ __forceinline__ float dot4(float4 a, float4 b) {
    return a.x * b.x + a.y * b.y + a.z * b.z + a.w * b.w;
}

// Packed fp32x2 FMA (sm_103a FFMA2 — PTX-only)
__device__ __forceinline__ void ffma2(unsigned long long& d,
                                      unsigned long long a,
                                      unsigned long long b) {
    asm("fma.rn.f32x2 %0, %1, %2, %0;" : "+l"(d) : "l"(a), "l"(b));
}
__device__ __forceinline__ unsigned long long bcast2(float x) {
    unsigned long long r;
    asm("mov.b64 %0, {%1, %1};" : "=l"(r) : "f"(x));
    return r;
}
__device__ __forceinline__ void unpack2(unsigned long long v, float& lo, float& hi) {
    asm("mov.b64 {%0, %1}, %2;" : "=f"(lo), "=f"(hi) : "l"(v));
}

// ---------------------------------------------------------------------------
// Kernel 1: fused rank-1 projections — best measured config (6.8 TB/s).
// ---------------------------------------------------------------------------
__global__ void __launch_bounds__(256) proj_kernel(
    const float* __restrict__ xq, const float* __restrict__ xk,
    const float* __restrict__ xv, const float* __restrict__ WQ,
    const float* __restrict__ WK, const float* __restrict__ WV)
{
    __shared__ float sW[3][D];
    int tid = threadIdx.x;
    sW[0][tid] = WQ[tid];
    sW[1][tid] = WK[tid];
    sW[2][tid] = WV[tid];
    __syncthreads();

    const int warp = tid >> 5;
    const int lane = tid & 31;
    const long long stride = (long long)PROJ_BLOCKS * 8;
    const long long total = 3LL * N * N;

    for (long long row = (long long)blockIdx.x * 8 + warp; row < total; row += stride) {
        int t = (int)(row >> 18);
        int r = (int)(row & (N * N - 1));

        const float* x = (t == 0) ? xq : (t == 1) ? xk : xv;
        const float4* xr = reinterpret_cast<const float4*>(x + (size_t)r * D);
        const float4* w4 = reinterpret_cast<const float4*>(sW[t]);

        float4 a0 = __ldcs(&xr[lane]);
        float4 a1 = __ldcs(&xr[lane + 32]);
        float4 b0 = w4[lane];
        float4 b1 = w4[lane + 32];

        float acc = dot4(a0, b0) + dot4(a1, b1);

#pragma unroll
        for (int o = 16; o > 0; o >>= 1)
            acc += __shfl_xor_sync(0xffffffffu, acc, o);

        if (lane == 0) {
            float* g = (t == 0) ? g_q : (t == 1) ? g_k : g_v;
            g[r] = acc;
        }
    }
}

// ---------------------------------------------------------------------------
// Kernel 2/4: split-K SGEMM partials, FFMA2 + software-pipelined kk loop.
// BM=128, BN=64, BK=32; 256 threads; 8x4 microtile as 4x4 f32x2 pairs.
// As rows permuted [0,4,1,5,2,6,3,7] per 8-row group -> one LDS.128 yields
// two (row i, row i+4) f32x2 operands. grid (8,4,KSPLIT)=256.
// ---------------------------------------------------------------------------
__global__ void __launch_bounds__(256, 2) sgemm_kernel(int mode)
{
    const float* __restrict__ A = (mode == 0) ? g_q : g_s;
    const float* __restrict__ B = (mode == 0) ? g_k : g_v;
    float* __restrict__ C = (mode == 0) ? g_sp[blockIdx.z] : g_op[blockIdx.z];

    __shared__ float As[32][136];   // [k][perm(m)]
    __shared__ float Bs[32][64];    // [k][n]

    const int bx = blockIdx.x * 64;
    const int by = blockIdx.y * 128;
    const int kbase = blockIdx.z * (N / KSPLIT);
    const int tid = threadIdx.x;
    const int tx = tid & 15;
    const int ty = tid >> 4;

    const int am = tid >> 1;
    const int pm = (am & ~7) | ((am & 3) << 1) | ((am >> 2) & 1);
    const int ah = (tid & 1) * 16;
    const int bn = (tid & 15) * 4;
    const int bk = tid >> 4;

    float4 aR[4];
#pragma unroll
    for (int j = 0; j < 4; j++)
        aR[j] = *(const float4*)&A[(by + am) * N + kbase + ah + j * 4];
    float4 b0 = *(const float4*)&B[(kbase + bk) * N + bx + bn];
    float4 b1 = *(const float4*)&B[(kbase + bk + 16) * N + bx + bn];

    unsigned long long accp[4][4];
#pragma unroll
    for (int p = 0; p < 4; p++)
#pragma unroll
        for (int j = 0; j < 4; j++)
            accp[p][j] = 0ULL;

    for (int k0 = 0; k0 < N / KSPLIT; k0 += 32) {
#pragma unroll
        for (int j = 0; j < 4; j++) {
            As[ah + j * 4 + 0][pm] = aR[j].x;
            As[ah + j * 4 + 1][pm] = aR[j].y;
            As[ah + j * 4 + 2][pm] = aR[j].z;
            As[ah + j * 4 + 3][pm] = aR[j].w;
        }
        *(float4*)&Bs[bk][bn]      = b0;
        *(float4*)&Bs[bk + 16][bn] = b1;
        __syncthreads();

        if (k0 + 32 < N / KSPLIT) {
            int kn = kbase + k0 + 32;
#pragma unroll
            for (int j = 0; j < 4; j++)
                aR[j] = *(const float4*)&A[(by + am) * N + kn + ah + j * 4];
            b0 = *(const float4*)&B[(kn + bk) * N + bx + bn];
            b1 = *(const float4*)&B[(kn + bk + 16) * N + bx + bn];
        }

        // Software-pipelined kk loop: operands for kk+1 are loaded before
        // kk's FFMA2 block, putting ~20 instructions between LDS and use.
        ulonglong2 a01 = *(const ulonglong2*)&As[0][ty * 8];
        ulonglong2 a23 = *(const ulonglong2*)&As[0][ty * 8 + 4];
        float4 bq = *(const float4*)&Bs[0][tx * 4];

#pragma unroll
        for (int kk = 0; kk < 32; kk++) {
            ulonglong2 na01, na23;
            float4 nb;
            if (kk < 31) {
                na01 = *(const ulonglong2*)&As[kk + 1][ty * 8];
                na23 = *(const ulonglong2*)&As[kk + 1][ty * 8 + 4];
                nb   = *(const float4*)&Bs[kk + 1][tx * 4];
            }

            unsigned long long a2[4] = { a01.x, a01.y, a23.x, a23.y };
            unsigned long long b2[4] = { bcast2(bq.x), bcast2(bq.y),
                                         bcast2(bq.z), bcast2(bq.w) };
#pragma unroll
            for (int p = 0; p < 4; p++)
#pragma unroll
                for (int j = 0; j < 4; j++)
                    ffma2(accp[p][j], a2[p], b2[j]);

            if (kk < 31) {
                a01 = na01;
                a23 = na23;
                bq = nb;
            }
        }
        __syncthreads();
    }

    // Epilogue: pair p holds (row ty*8+p, row ty*8+4+p)
#pragma unroll
    for (int p = 0; p < 4; p++) {
        float lo[4], hi[4];
#pragma unroll
        for (int j = 0; j < 4; j++)
            unpack2(accp[p][j], lo[j], hi[j]);
        *(float4*)&C[(by + ty * 8 + p) * N + bx + tx * 4] =
            make_float4(lo[0], lo[1], lo[2], lo[3]);
        *(float4*)&C[(by + ty * 8 + 4 + p) * N + bx + tx * 4] =
            make_float4(hi[0], hi[1], hi[2], hi[3]);
    }
}

// ---------------------------------------------------------------------------
// Kernel 3: sum KSPLIT s-partials + row softmax -> g_s.
// ---------------------------------------------------------------------------
__global__ void __launch_bounds__(256) softmax_kernel()
{
    __shared__ float smax[2][4];
    __shared__ float ssum[2][4];

    const int tid = threadIdx.x;
    const int half = tid >> 7;
    const int t = tid & 127;
    const int warp = (tid >> 5) & 3;
    const int lane = tid & 31;
    const int row = blockIdx.x * 2 + half;
    const size_t off = (size_t)row * N + t * 4;

    float4 a = make_float4(0.f, 0.f, 0.f, 0.f);
#pragma unroll
    for (int z = 0; z < KSPLIT; z++) {
        float4 p = *(const float4*)&g_sp[z][off];
        a.x += p.x; a.y += p.y; a.z += p.z; a.w += p.w;
    }

    float mx = fmaxf(fmaxf(a.x, a.y), fmaxf(a.z, a.w));
#pragma unroll
    for (int o = 16; o > 0; o >>= 1)
        mx = fmaxf(mx, __shfl_xor_sync(0xffffffffu, mx, o));
    if (lane == 0) smax[half][warp] = mx;
    __syncthreads();
    mx = fmaxf(fmaxf(smax[half][0], smax[half][1]),
               fmaxf(smax[half][2], smax[half][3]));

    float4 e;
    e.x = __expf(a.x - mx);
    e.y = __expf(a.y - mx);
    e.z = __expf(a.z - mx);
    e.w = __expf(a.w - mx);

    float s = e.x + e.y + e.z + e.w;
#pragma unroll
    for (int o = 16; o > 0; o >>= 1)
        s += __shfl_xor_sync(0xffffffffu, s, o);
    if (lane == 0) ssum[half][warp] = s;
    __syncthreads();
    float inv = 1.0f / (ssum[half][0] + ssum[half][1] + ssum[half][2] + ssum[half][3]);

    e.x *= inv; e.y *= inv; e.z *= inv; e.w *= inv;
    *(float4*)&g_s[off] = e;
}

// ---------------------------------------------------------------------------
// Kernel 5: sum KSPLIT out-partials -> d_out.
// ---------------------------------------------------------------------------
__global__ void __launch_bounds__(256) reduce_out_kernel(float* __restrict__ out)
{
    int i = blockIdx.x * 256 + threadIdx.x;
    float4 r = ((const float4*)g_op[0])[i];
#pragma unroll
    for (int z = 1; z < KSPLIT; z++) {
        float4 s = ((const float4*)g_op[z])[i];
        r.x += s.x; r.y += s.y; r.z += s.z; r.w += s.w;
    }
    ((float4*)out)[i] = r;
}

// ---------------------------------------------------------------------------
extern "C" void kernel_launch(void* const* d_in, const int* in_sizes, int n_in,
                              void* d_out, int out_size)
{
    const float* xq = (const float*)d_in[0];
    const float* xk = (const float*)d_in[1];
    const float* xv = (const float*)d_in[2];
    const float* WQ = (const float*)d_in[3];
    const float* WK = (const float*)d_in[4];
    const float* WV = (const float*)d_in[5];
    float* out = (float*)d_out;

    proj_kernel<<<PROJ_BLOCKS, 256>>>(xq, xk, xv, WQ, WK, WV);

    dim3 gg(N / 64, N / 128, KSPLIT);   // (8, 4, 8) = 256 blocks
    sgemm_kernel<<<gg, 256>>>(0);

    softmax_kernel<<<N / 2, 256>>>();

    sgemm_kernel<<<gg, 256>>>(1);

    reduce_out_kernel<<<(N * N / 4) / 256, 256>>>(out);
}